// round 3
// baseline (speedup 1.0000x reference)
#include <cuda_runtime.h>
#include <cstdint>

#define MAXN 100000
#define DD 64

// ---- scratch (no allocations allowed) ----
__device__ __align__(16) float  g_hbuf[(size_t)MAXN * DD];   // h = (1+eps)*x + scatter [N,64]
__device__ __align__(16) float  g_h1[(size_t)MAXN * 2 * DD]; // pre-BN hidden           [N,128]
__device__ double g_sum[2 * DD];
__device__ double g_sq[2 * DD];
__device__ float  g_scale[2 * DD];
__device__ float  g_shift[2 * DD];
__device__ int    g_is64;                                    // 1 if edge buffers are int64

// ---------------------------------------------------------------------------
// K0: dtype probe. edge_feats values are tiny (0/1). Read 32 int64 words:
// if all in [0,7] -> data really is int64; else it was downcast to int32.
// ---------------------------------------------------------------------------
__global__ void k_probe(const long long* __restrict__ ef)
{
    int ok = 1;
#pragma unroll
    for (int i = 0; i < 32; i++) {
        long long v = ef[i];
        if (v < 0 || v > 7) ok = 0;
    }
    g_is64 = ok;
}

// ---------------------------------------------------------------------------
// K1: h = (1+eps)*node_feats ; zero BN accumulators
// ---------------------------------------------------------------------------
__global__ void k_init(const float* __restrict__ nf, const float* __restrict__ eps, int n4)
{
    int i = blockIdx.x * blockDim.x + threadIdx.x;
    if (i < 128) { g_sum[i] = 0.0; g_sq[i] = 0.0; }
    if (i < n4) {
        float s = 1.0f + eps[0];
        float4 v = ((const float4*)nf)[i];
        v.x *= s; v.y *= s; v.z *= s; v.w *= s;
        ((float4*)g_hbuf)[i] = v;
    }
}

// ---------------------------------------------------------------------------
// K2: edge messages + scatter-add.  2 edges per warp, 16 lanes x float4 each.
// message = relu(nf[src] + emb0[f0] + emb1[f1] + emb2[f2]); red.add -> hbuf[dst]
// Index dtype (int32 vs int64) resolved via g_is64 (uniform branch).
// ---------------------------------------------------------------------------
__global__ void k_edge(const float4* __restrict__ nf4,
                       const void* __restrict__ ef,    // [E,3]
                       const void* __restrict__ ei,    // [2,E]: row0=dst, row1=src
                       const float4* __restrict__ e0,
                       const float4* __restrict__ e1,
                       const float4* __restrict__ e2,
                       long long E, int Nn)
{
    int lane = threadIdx.x & 31;
    long long warpId = (long long)blockIdx.x * (blockDim.x >> 5) + (threadIdx.x >> 5);
    int half = lane >> 4;          // which of the 2 edges
    int q    = lane & 15;          // float4 index within the 64-float row
    long long e = warpId * 2 + half;

    int src = 0, dst = 0, f0 = 0, f1 = 0, f2 = 0;
    if (q == 0 && e < E) {
        if (g_is64) {
            const long long* ei64 = (const long long*)ei;
            const long long* ef64 = (const long long*)ef + e * 3;
            dst = (int)ei64[e];
            src = (int)ei64[E + e];
            f0 = (int)ef64[0]; f1 = (int)ef64[1]; f2 = (int)ef64[2];
        } else {
            const int* ei32 = (const int*)ei;
            const int* ef32 = (const int*)ef + e * 3;
            dst = ei32[e];
            src = ei32[E + e];
            f0 = ef32[0]; f1 = ef32[1]; f2 = ef32[2];
        }
    }
    int leader = half << 4;
    dst = __shfl_sync(0xffffffffu, dst, leader);
    src = __shfl_sync(0xffffffffu, src, leader);
    f0  = __shfl_sync(0xffffffffu, f0,  leader);
    f1  = __shfl_sync(0xffffffffu, f1,  leader);
    f2  = __shfl_sync(0xffffffffu, f2,  leader);
    if (e >= E) return;
    if ((unsigned)src >= (unsigned)Nn || (unsigned)dst >= (unsigned)Nn) return;
    if ((unsigned)f0 > 4u || (unsigned)f1 > 5u || (unsigned)f2 > 1u) return;

    float4 a = e0[f0 * 16 + q];
    float4 b = e1[f1 * 16 + q];
    float4 c = e2[f2 * 16 + q];
    float4 n = nf4[(long long)src * 16 + q];

    float x = fmaxf(n.x + a.x + b.x + c.x, 0.0f);
    float y = fmaxf(n.y + a.y + b.y + c.y, 0.0f);
    float z = fmaxf(n.z + a.z + b.z + c.z, 0.0f);
    float w = fmaxf(n.w + a.w + b.w + c.w, 0.0f);

    float* p = g_hbuf + (long long)dst * 64 + q * 4;
    asm volatile("red.global.add.v4.f32 [%0], {%1,%2,%3,%4};"
                 :: "l"(p), "f"(x), "f"(y), "f"(z), "f"(w) : "memory");
}

// ---------------------------------------------------------------------------
// K3: h1 = h @ W1^T + b1, store h1 and accumulate per-channel sum / sumsq.
// blockDim=128 (thread j = output channel). W1 in smem, row stride 68
// (17 odd -> conflict-free LDS.128 across a warp). 4 rows per iteration.
// ---------------------------------------------------------------------------
__global__ void k_gemm1(const float* __restrict__ W1,  // [128,64]
                        const float* __restrict__ b1,
                        int N)
{
    __shared__ float  Wsh[128 * 68];
    __shared__ float4 hsh[4 * 16];
    int tid = threadIdx.x;

    for (int i = tid; i < 128 * 64; i += 128)
        Wsh[(i >> 6) * 68 + (i & 63)] = W1[i];
    float bj = b1[tid];

    float lsum = 0.0f, lsq = 0.0f;

    for (long long r0 = (long long)blockIdx.x * 4; r0 < N; r0 += (long long)gridDim.x * 4) {
        __syncthreads();
        for (int i = tid; i < 4 * 64; i += 128) {
            long long row = r0 + (i >> 6);
            ((float*)hsh)[i] = (row < N) ? g_hbuf[row * 64 + (i & 63)] : 0.0f;
        }
        __syncthreads();

        const float4* wr = (const float4*)(Wsh + tid * 68);
        float a0 = bj, a1 = bj, a2 = bj, a3 = bj;
#pragma unroll
        for (int k4 = 0; k4 < 16; k4++) {
            float4 w  = wr[k4];
            float4 h0 = hsh[k4];
            float4 h1 = hsh[16 + k4];
            float4 h2 = hsh[32 + k4];
            float4 h3 = hsh[48 + k4];
            a0 += w.x * h0.x + w.y * h0.y + w.z * h0.z + w.w * h0.w;
            a1 += w.x * h1.x + w.y * h1.y + w.z * h1.z + w.w * h1.w;
            a2 += w.x * h2.x + w.y * h2.y + w.z * h2.z + w.w * h2.w;
            a3 += w.x * h3.x + w.y * h3.y + w.z * h3.z + w.w * h3.w;
        }
        long long base = r0 * 128 + tid;
        if (r0 + 0 < N) { g_h1[base          ] = a0; lsum += a0; lsq += a0 * a0; }
        if (r0 + 1 < N) { g_h1[base + 128    ] = a1; lsum += a1; lsq += a1 * a1; }
        if (r0 + 2 < N) { g_h1[base + 256    ] = a2; lsum += a2; lsq += a2 * a2; }
        if (r0 + 3 < N) { g_h1[base + 384    ] = a3; lsum += a3; lsq += a3 * a3; }
    }
    atomicAdd(&g_sum[tid], (double)lsum);
    atomicAdd(&g_sq[tid],  (double)lsq);
}

// ---------------------------------------------------------------------------
// K4: fold BN into per-channel scale/shift.
// ---------------------------------------------------------------------------
__global__ void k_bn(const float* __restrict__ gamma, const float* __restrict__ beta, double invN)
{
    int j = threadIdx.x;
    float mean = (float)(g_sum[j] * invN);
    float var  = (float)(g_sq[j]  * invN) - mean * mean;
    float inv  = rsqrtf(var + 1e-5f);
    float sc   = gamma[j] * inv;
    g_scale[j] = sc;
    g_shift[j] = beta[j] - mean * sc;
}

// ---------------------------------------------------------------------------
// K5: out = relu(scale*h1 + shift) @ W2^T + b2.
// blockDim=128: two groups of 64 threads, 8 rows per iteration.
// W2 in smem, row stride 132 (33 odd -> conflict-free across warp).
// ---------------------------------------------------------------------------
__global__ void k_gemm2(const float* __restrict__ W2,  // [64,128]
                        const float* __restrict__ b2,
                        float* __restrict__ out,
                        int N)
{
    __shared__ float  Wsh[64 * 132];
    __shared__ float4 ash[8 * 32];
    __shared__ float  sc[128], sh[128];
    int tid = threadIdx.x;

    for (int i = tid; i < 64 * 128; i += 128)
        Wsh[(i >> 7) * 132 + (i & 127)] = W2[i];
    sc[tid] = g_scale[tid];
    sh[tid] = g_shift[tid];

    int g = tid >> 6;        // row group 0/1
    int i = tid & 63;        // output channel
    float bi = b2[i];

    for (long long r0 = (long long)blockIdx.x * 8; r0 < N; r0 += (long long)gridDim.x * 8) {
        __syncthreads();
        for (int t = tid; t < 8 * 128; t += 128) {
            int j = t & 127;
            long long row = r0 + (t >> 7);
            float v = (row < N) ? g_h1[row * 128 + j] : 0.0f;
            ((float*)ash)[t] = fmaxf(fmaf(sc[j], v, sh[j]), 0.0f);
        }
        __syncthreads();

        const float4* wr = (const float4*)(Wsh + i * 132);
        int rb = g * 4;
        float a0 = bi, a1 = bi, a2 = bi, a3 = bi;
#pragma unroll
        for (int j4 = 0; j4 < 32; j4++) {
            float4 w = wr[j4];
            float4 v0 = ash[(rb + 0) * 32 + j4];
            float4 v1 = ash[(rb + 1) * 32 + j4];
            float4 v2 = ash[(rb + 2) * 32 + j4];
            float4 v3 = ash[(rb + 3) * 32 + j4];
            a0 += w.x * v0.x + w.y * v0.y + w.z * v0.z + w.w * v0.w;
            a1 += w.x * v1.x + w.y * v1.y + w.z * v1.z + w.w * v1.w;
            a2 += w.x * v2.x + w.y * v2.y + w.z * v2.z + w.w * v2.w;
            a3 += w.x * v3.x + w.y * v3.y + w.z * v3.z + w.w * v3.w;
        }
        if (r0 + rb + 0 < N) out[(r0 + rb + 0) * 64 + i] = a0;
        if (r0 + rb + 1 < N) out[(r0 + rb + 1) * 64 + i] = a1;
        if (r0 + rb + 2 < N) out[(r0 + rb + 2) * 64 + i] = a2;
        if (r0 + rb + 3 < N) out[(r0 + rb + 3) * 64 + i] = a3;
    }
}

// ---------------------------------------------------------------------------
// Binding: size-driven anchor on the unique size-320 buffer (bond_emb0, 5x64);
// eps is the buffer immediately before it, then emb1, emb2, W1, b1, gamma,
// beta, W2, b2 follow in order. Robust to whether the integer scalars
// (num_nodes, num_edges) appear as buffers. Index dtype (int32/int64) is
// resolved on-device by k_probe.
// ---------------------------------------------------------------------------
extern "C" void kernel_launch(void* const* d_in, const int* in_sizes, int n_in,
                              void* d_out, int out_size)
{
    const float* nf = (const float*)d_in[0];
    const void*  ef = d_in[1];
    const void*  ei = d_in[2];

    int iEmb0 = -1;
    for (int i = 3; i < n_in; i++) {
        if (in_sizes[i] == 320) { iEmb0 = i; break; }
    }
    if (iEmb0 < 0) iEmb0 = 6;  // fallback: canonical layout

    const float* eps   = (const float*)d_in[iEmb0 - 1];
    const float* e0    = (const float*)d_in[iEmb0];
    const float* e1    = (const float*)d_in[iEmb0 + 1];
    const float* e2    = (const float*)d_in[iEmb0 + 2];
    const float* W1    = (const float*)d_in[iEmb0 + 3];
    const float* b1    = (const float*)d_in[iEmb0 + 4];
    const float* gamma = (const float*)d_in[iEmb0 + 5];
    const float* beta  = (const float*)d_in[iEmb0 + 6];
    const float* W2    = (const float*)d_in[iEmb0 + 7];
    const float* b2    = (const float*)d_in[iEmb0 + 8];

    int N = in_sizes[0] / 64;
    long long E = (long long)in_sizes[1] / 3;

    k_probe<<<1, 1>>>((const long long*)ef);

    int n4 = N * 16;
    k_init<<<(n4 + 255) / 256, 256>>>(nf, eps, n4);

    long long warpsNeeded = (E + 1) / 2;
    int eblocks = (int)((warpsNeeded + 7) / 8);
    k_edge<<<eblocks, 256>>>((const float4*)nf, ef, ei,
                             (const float4*)e0, (const float4*)e1, (const float4*)e2, E, N);

    k_gemm1<<<1184, 128>>>(W1, b1, N);
    k_bn<<<1, 128>>>(gamma, beta, 1.0 / (double)N);
    k_gemm2<<<1184, 128>>>(W2, b2, (float*)d_out, N);
}

// round 5
// speedup vs baseline: 1.2607x; 1.2607x over previous
#include <cuda_runtime.h>
#include <cstdint>

#define MAXN 100000
#define DD 64

// ---- scratch (no allocations allowed) ----
__device__ __align__(16) float  g_hbuf[(size_t)MAXN * DD];   // h = (1+eps)*x + scatter [N,64]
__device__ __align__(16) float  g_h1[(size_t)MAXN * 2 * DD]; // pre-BN hidden           [N,128]
__device__ double g_sum[2 * DD];
__device__ double g_sq[2 * DD];
__device__ float  g_scale[2 * DD];
__device__ float  g_shift[2 * DD];
__device__ int    g_is64;                                    // 1 if edge buffers are int64

// ---------------------------------------------------------------------------
// K0: dtype probe. edge_feats values are tiny (0/1). Read 32 int64 words:
// if all in [0,7] -> data really is int64; else it was downcast to int32.
// ---------------------------------------------------------------------------
__global__ void k_probe(const long long* __restrict__ ef)
{
    int ok = 1;
#pragma unroll
    for (int i = 0; i < 32; i++) {
        long long v = ef[i];
        if (v < 0 || v > 7) ok = 0;
    }
    g_is64 = ok;
}

// ---------------------------------------------------------------------------
// K1: h = (1+eps)*node_feats ; zero BN accumulators
// ---------------------------------------------------------------------------
__global__ void k_init(const float* __restrict__ nf, const float* __restrict__ eps, int n4)
{
    int i = blockIdx.x * blockDim.x + threadIdx.x;
    if (i < 128) { g_sum[i] = 0.0; g_sq[i] = 0.0; }
    if (i < n4) {
        float s = 1.0f + eps[0];
        float4 v = ((const float4*)nf)[i];
        v.x *= s; v.y *= s; v.z *= s; v.w *= s;
        ((float4*)g_hbuf)[i] = v;
    }
}

// ---------------------------------------------------------------------------
// K2: edge messages + scatter-add.  2 edges per warp, 16 lanes x float4 each.
// ---------------------------------------------------------------------------
__global__ void k_edge(const float4* __restrict__ nf4,
                       const void* __restrict__ ef,    // [E,3]
                       const void* __restrict__ ei,    // [2,E]: row0=dst, row1=src
                       const float4* __restrict__ e0,
                       const float4* __restrict__ e1,
                       const float4* __restrict__ e2,
                       long long E, int Nn)
{
    int lane = threadIdx.x & 31;
    long long warpId = (long long)blockIdx.x * (blockDim.x >> 5) + (threadIdx.x >> 5);
    int half = lane >> 4;
    int q    = lane & 15;
    long long e = warpId * 2 + half;

    int src = 0, dst = 0, f0 = 0, f1 = 0, f2 = 0;
    if (q == 0 && e < E) {
        if (g_is64) {
            const long long* ei64 = (const long long*)ei;
            const long long* ef64 = (const long long*)ef + e * 3;
            dst = (int)ei64[e];
            src = (int)ei64[E + e];
            f0 = (int)ef64[0]; f1 = (int)ef64[1]; f2 = (int)ef64[2];
        } else {
            const int* ei32 = (const int*)ei;
            const int* ef32 = (const int*)ef + e * 3;
            dst = ei32[e];
            src = ei32[E + e];
            f0 = ef32[0]; f1 = ef32[1]; f2 = ef32[2];
        }
    }
    int leader = half << 4;
    dst = __shfl_sync(0xffffffffu, dst, leader);
    src = __shfl_sync(0xffffffffu, src, leader);
    f0  = __shfl_sync(0xffffffffu, f0,  leader);
    f1  = __shfl_sync(0xffffffffu, f1,  leader);
    f2  = __shfl_sync(0xffffffffu, f2,  leader);
    if (e >= E) return;
    if ((unsigned)src >= (unsigned)Nn || (unsigned)dst >= (unsigned)Nn) return;
    if ((unsigned)f0 > 4u || (unsigned)f1 > 5u || (unsigned)f2 > 1u) return;

    float4 a = e0[f0 * 16 + q];
    float4 b = e1[f1 * 16 + q];
    float4 c = e2[f2 * 16 + q];
    float4 n = nf4[(long long)src * 16 + q];

    float x = fmaxf(n.x + a.x + b.x + c.x, 0.0f);
    float y = fmaxf(n.y + a.y + b.y + c.y, 0.0f);
    float z = fmaxf(n.z + a.z + b.z + c.z, 0.0f);
    float w = fmaxf(n.w + a.w + b.w + c.w, 0.0f);

    float* p = g_hbuf + (long long)dst * 64 + q * 4;
    asm volatile("red.global.add.v4.f32 [%0], {%1,%2,%3,%4};"
                 :: "l"(p), "f"(x), "f"(y), "f"(z), "f"(w) : "memory");
}

// ---------------------------------------------------------------------------
// K3 v2: h1 = h @ W1^T + b1 + BN stats.
// Thread j = output channel. W1 row j lives in 16 float4 REGISTERS (loaded
// once per block); inner loop touches shared only via broadcast LDS (all
// threads read the same hsh address -> conflict-free, 1 phase).
// 8 rows per iteration, 8 independent accumulators (ILP=8).
// ---------------------------------------------------------------------------
__global__ void __launch_bounds__(128) k_gemm1(const float* __restrict__ W1,  // [128,64]
                                               const float* __restrict__ b1,
                                               int N)
{
    __shared__ float4 hsh[8 * 16];  // 8 rows x 64 floats
    int tid = threadIdx.x;

    float4 w[16];
#pragma unroll
    for (int k4 = 0; k4 < 16; k4++)
        w[k4] = ((const float4*)W1)[tid * 16 + k4];
    float bj = __ldg(b1 + tid);

    float lsum = 0.0f, lsq = 0.0f;

    for (long long r0 = (long long)blockIdx.x * 8; r0 < N; r0 += (long long)gridDim.x * 8) {
        __syncthreads();
        {
            long long row = r0 + (tid >> 4);
            int k4 = tid & 15;
            hsh[tid] = (row < N) ? ((const float4*)g_hbuf)[row * 16 + k4]
                                 : make_float4(0.f, 0.f, 0.f, 0.f);
        }
        __syncthreads();

        float acc[8];
#pragma unroll
        for (int r = 0; r < 8; r++) acc[r] = bj;
#pragma unroll
        for (int k4 = 0; k4 < 16; k4++) {
            float4 wv = w[k4];
#pragma unroll
            for (int r = 0; r < 8; r++) {
                float4 h = hsh[r * 16 + k4];
                acc[r] += wv.x * h.x + wv.y * h.y + wv.z * h.z + wv.w * h.w;
            }
        }

        long long base = r0 * 128 + tid;
#pragma unroll
        for (int r = 0; r < 8; r++) {
            if (r0 + r < N) {
                float a = acc[r];
                g_h1[base + r * 128] = a;   // warp writes 128B contiguous: coalesced
                lsum += a; lsq += a * a;
            }
        }
    }
    atomicAdd(&g_sum[tid], (double)lsum);
    atomicAdd(&g_sq[tid],  (double)lsq);
}

// ---------------------------------------------------------------------------
// K4: fold BN into per-channel scale/shift.
// ---------------------------------------------------------------------------
__global__ void k_bn(const float* __restrict__ gamma, const float* __restrict__ beta, double invN)
{
    int j = threadIdx.x;
    float mean = (float)(g_sum[j] * invN);
    float var  = (float)(g_sq[j]  * invN) - mean * mean;
    float inv  = rsqrtf(var + 1e-5f);
    float sc   = gamma[j] * inv;
    g_scale[j] = sc;
    g_shift[j] = beta[j] - mean * sc;
}

// ---------------------------------------------------------------------------
// K5 v2: out = relu(scale*h1 + shift) @ W2^T + b2.
// Thread t: i = t&63 (output channel), hh = t>>6 (input half). Each thread
// holds half of W2 row i (64 floats) in registers; halves combined through a
// small smem partial buffer. Inner loop: broadcast LDS only.
// ---------------------------------------------------------------------------
__global__ void __launch_bounds__(128) k_gemm2(const float* __restrict__ W2,  // [64,128]
                                               const float* __restrict__ b2,
                                               float* __restrict__ out,
                                               int N)
{
    __shared__ float4 ash[8 * 32];      // 8 rows x 128 activations
    __shared__ float  sc[128], sh[128];
    __shared__ float  partial[8 * 64];
    int tid = threadIdx.x;
    int i  = tid & 63;
    int hh = tid >> 6;

    float4 w[16];
#pragma unroll
    for (int k4 = 0; k4 < 16; k4++)
        w[k4] = ((const float4*)W2)[i * 32 + hh * 16 + k4];
    sc[tid] = g_scale[tid];
    sh[tid] = g_shift[tid];
    float bi = __ldg(b2 + i);
    __syncthreads();

    for (long long r0 = (long long)blockIdx.x * 8; r0 < N; r0 += (long long)gridDim.x * 8) {
        __syncthreads();
#pragma unroll
        for (int t = 0; t < 2; t++) {
            int idx = tid + t * 128;        // float4 slot in 8x32
            int j4  = idx & 31;
            long long row = r0 + (idx >> 5);
            float4 v = (row < N) ? ((const float4*)g_h1)[row * 32 + j4]
                                 : make_float4(0.f, 0.f, 0.f, 0.f);
            int j = j4 * 4;
            v.x = fmaxf(fmaf(sc[j + 0], v.x, sh[j + 0]), 0.0f);
            v.y = fmaxf(fmaf(sc[j + 1], v.y, sh[j + 1]), 0.0f);
            v.z = fmaxf(fmaf(sc[j + 2], v.z, sh[j + 2]), 0.0f);
            v.w = fmaxf(fmaf(sc[j + 3], v.w, sh[j + 3]), 0.0f);
            ash[idx] = v;
        }
        __syncthreads();

        float acc[8];
#pragma unroll
        for (int r = 0; r < 8; r++) acc[r] = 0.0f;
#pragma unroll
        for (int k4 = 0; k4 < 16; k4++) {
            float4 wv = w[k4];
#pragma unroll
            for (int r = 0; r < 8; r++) {
                float4 h = ash[r * 32 + hh * 16 + k4];  // broadcast within warp
                acc[r] += wv.x * h.x + wv.y * h.y + wv.z * h.z + wv.w * h.w;
            }
        }

        if (hh == 1) {
#pragma unroll
            for (int r = 0; r < 8; r++) partial[r * 64 + i] = acc[r];
        }
        __syncthreads();
        if (hh == 0) {
#pragma unroll
            for (int r = 0; r < 8; r++) {
                if (r0 + r < N)
                    out[(r0 + r) * 64 + i] = acc[r] + partial[r * 64 + i] + bi;
            }
        }
    }
}

// ---------------------------------------------------------------------------
// Binding: size-driven anchor on the unique size-320 buffer (bond_emb0).
// ---------------------------------------------------------------------------
extern "C" void kernel_launch(void* const* d_in, const int* in_sizes, int n_in,
                              void* d_out, int out_size)
{
    const float* nf = (const float*)d_in[0];
    const void*  ef = d_in[1];
    const void*  ei = d_in[2];

    int iEmb0 = -1;
    for (int i = 3; i < n_in; i++) {
        if (in_sizes[i] == 320) { iEmb0 = i; break; }
    }
    if (iEmb0 < 0) iEmb0 = 6;

    const float* eps   = (const float*)d_in[iEmb0 - 1];
    const float* e0    = (const float*)d_in[iEmb0];
    const float* e1    = (const float*)d_in[iEmb0 + 1];
    const float* e2    = (const float*)d_in[iEmb0 + 2];
    const float* W1    = (const float*)d_in[iEmb0 + 3];
    const float* b1    = (const float*)d_in[iEmb0 + 4];
    const float* gamma = (const float*)d_in[iEmb0 + 5];
    const float* beta  = (const float*)d_in[iEmb0 + 6];
    const float* W2    = (const float*)d_in[iEmb0 + 7];
    const float* b2    = (const float*)d_in[iEmb0 + 8];

    int N = in_sizes[0] / 64;
    long long E = (long long)in_sizes[1] / 3;

    k_probe<<<1, 1>>>((const long long*)ef);

    int n4 = N * 16;
    k_init<<<(n4 + 255) / 256, 256>>>(nf, eps, n4);

    long long warpsNeeded = (E + 1) / 2;
    int eblocks = (int)((warpsNeeded + 7) / 8);
    k_edge<<<eblocks, 256>>>((const float4*)nf, ef, ei,
                             (const float4*)e0, (const float4*)e1, (const float4*)e2, E, N);

    k_gemm1<<<592, 128>>>(W1, b1, N);
    k_bn<<<1, 128>>>(gamma, beta, 1.0 / (double)N);
    k_gemm2<<<592, 128>>>(W2, b2, (float*)d_out, N);
}